// round 2
// baseline (speedup 1.0000x reference)
#include <cuda_runtime.h>
#include <cstdint>

// ---------------------------------------------------------------------------
// GCN: 3 layers of  h = relu(segment_sum_{(s->d)}(h_prev[s]) @ W + b)
// (aggregate-before-transform: segment_sum is linear, so this equals the
//  reference's transform-then-aggregate.)
// ---------------------------------------------------------------------------

#define N_NODES 50000
#define N_EDGES 800000
#define FMAX    256

// Scratch (static device globals — no runtime allocation).
__device__ float g_h[(size_t)N_NODES * FMAX];    // layer activations
__device__ float g_agg[(size_t)N_NODES * FMAX];  // per-layer aggregation
__device__ int   g_idx_is64;                     // 1 if edge_index is int64

// ---------------------------------------------------------------------------
// Edge-index dtype probe. JAX default config downcasts jnp.int64 -> int32,
// so the buffer may be either. Interpreting int32 data as int64 combines two
// indices (lo + hi*2^32); hi>0 for any nonzero second index, so the value
// blows past N_NODES. All-256-valid => genuinely int64.
// Only scans the first 256 int64 slots (always in-bounds for either dtype).
// ---------------------------------------------------------------------------
__global__ void detect_idx_dtype(const long long* __restrict__ ei64)
{
    if (threadIdx.x == 0 && blockIdx.x == 0) {
        int ok = 1;
        for (int i = 0; i < 256; i++) {
            long long v = ei64[i];
            if (v < 0 || v >= N_NODES) { ok = 0; break; }
        }
        g_idx_is64 = ok;
    }
}

// ---------------------------------------------------------------------------
// Scatter-sum: agg[dst] += h[src], vectorized float4 + vector atomics.
// One thread handles one float4 chunk of one edge.
// ---------------------------------------------------------------------------
template <int F>
__global__ __launch_bounds__(256) void scatter_kernel(
    const float* __restrict__ h,
    const void* __restrict__ edge_index,   // [2, N_EDGES], int32 or int64
    float* __restrict__ agg)
{
    constexpr int CH = F / 4;                    // float4 chunks per edge
    long long tid = (long long)blockIdx.x * blockDim.x + threadIdx.x;
    long long total = (long long)N_EDGES * CH;
    if (tid >= total) return;
    int e = (int)(tid / CH);
    int c = (int)(tid % CH);

    long long s, d;
    if (g_idx_is64) {
        const long long* ei = (const long long*)edge_index;
        s = ei[e];
        d = ei[N_EDGES + e];
    } else {
        const int* ei = (const int*)edge_index;
        s = ei[e];
        d = ei[N_EDGES + e];
    }
    // Safety: degrade to wrong-answer instead of crash if theory is wrong.
    if ((unsigned long long)s >= N_NODES || (unsigned long long)d >= N_NODES)
        return;

    float4 v = *reinterpret_cast<const float4*>(h + (size_t)s * F + (size_t)c * 4);
    float* p = agg + (size_t)d * F + (size_t)c * 4;
    // Vectorized reduction (sm_90+): one L2 atomic transaction for 16 bytes.
    asm volatile("red.global.add.v4.f32 [%0], {%1, %2, %3, %4};"
                 :: "l"(p), "f"(v.x), "f"(v.y), "f"(v.z), "f"(v.w)
                 : "memory");
}

// ---------------------------------------------------------------------------
// Tiled fp32 GEMM + bias + ReLU:  C[M,N] = relu(A[M,K] @ W[K,N] + b[N])
// BM=64, BN=64, BK=16, 256 threads, 4x4 microtile per thread.
// N % 64 == 0 and K % 16 == 0 always hold here (N=256, K=128/256).
// ---------------------------------------------------------------------------
#define BM 64
#define BN 64
#define BK 16

__global__ __launch_bounds__(256) void gemm_bias_relu(
    const float* __restrict__ A,
    const float* __restrict__ W,
    const float* __restrict__ bias,
    float* __restrict__ C,
    int M, int N, int K)
{
    __shared__ float As[BK][BM + 4];   // +4 pad: keeps 16B alignment, cuts conflicts
    __shared__ float Ws[BK][BN];

    int tid = threadIdx.x;
    int block_row = blockIdx.x * BM;
    int block_col = blockIdx.y * BN;

    // A-tile loads: 64 rows x 16 k, float4 along K per thread.
    int a_row = tid >> 2;            // 0..63
    int a_col = (tid & 3) * 4;       // 0,4,8,12
    // W-tile loads: 16 k x 64 n, float4 along N per thread.
    int w_row = tid >> 4;            // 0..15
    int w_col = (tid & 15) * 4;      // 0..60

    // Compute mapping: 16x16 thread grid, each owns a 4x4 output microtile.
    int tx = tid & 15;               // output col group
    int ty = tid >> 4;               // output row group

    float acc[4][4] = {};

    // Clamp tail-block row reads (stores are guarded below).
    int ga_row = block_row + a_row;
    if (ga_row >= M) ga_row = M - 1;
    const float* Arow = A + (size_t)ga_row * K;

    for (int k0 = 0; k0 < K; k0 += BK) {
        float4 av = *reinterpret_cast<const float4*>(Arow + k0 + a_col);
        As[a_col + 0][a_row] = av.x;
        As[a_col + 1][a_row] = av.y;
        As[a_col + 2][a_row] = av.z;
        As[a_col + 3][a_row] = av.w;

        float4 wv = *reinterpret_cast<const float4*>(
            W + (size_t)(k0 + w_row) * N + block_col + w_col);
        *reinterpret_cast<float4*>(&Ws[w_row][w_col]) = wv;

        __syncthreads();

        #pragma unroll
        for (int kk = 0; kk < BK; kk++) {
            float4 a = *reinterpret_cast<const float4*>(&As[kk][ty * 4]);
            float4 w = *reinterpret_cast<const float4*>(&Ws[kk][tx * 4]);
            acc[0][0] += a.x * w.x; acc[0][1] += a.x * w.y; acc[0][2] += a.x * w.z; acc[0][3] += a.x * w.w;
            acc[1][0] += a.y * w.x; acc[1][1] += a.y * w.y; acc[1][2] += a.y * w.z; acc[1][3] += a.y * w.w;
            acc[2][0] += a.z * w.x; acc[2][1] += a.z * w.y; acc[2][2] += a.z * w.z; acc[2][3] += a.z * w.w;
            acc[3][0] += a.w * w.x; acc[3][1] += a.w * w.y; acc[3][2] += a.w * w.z; acc[3][3] += a.w * w.w;
        }
        __syncthreads();
    }

    // Epilogue: bias + relu + guarded store.
    #pragma unroll
    for (int i = 0; i < 4; i++) {
        int row = block_row + ty * 4 + i;
        if (row >= M) continue;
        #pragma unroll
        for (int j = 0; j < 4; j++) {
            int col = block_col + tx * 4 + j;
            float v = acc[i][j] + bias[col];
            C[(size_t)row * N + col] = fmaxf(v, 0.0f);
        }
    }
}

// ---------------------------------------------------------------------------
// Launch orchestration
// ---------------------------------------------------------------------------
static inline void run_layer(const float* h_in, int Fin,
                             const void* edge_index,
                             const float* W, const float* b,
                             float* agg, float* h_out)
{
    // zero aggregation buffer
    cudaMemsetAsync(agg, 0, (size_t)N_NODES * Fin * sizeof(float), 0);

    // scatter
    long long work = (long long)N_EDGES * (Fin / 4);
    int blocks = (int)((work + 255) / 256);
    if (Fin == 128) {
        scatter_kernel<128><<<blocks, 256>>>(h_in, edge_index, agg);
    } else {
        scatter_kernel<256><<<blocks, 256>>>(h_in, edge_index, agg);
    }

    // transform + bias + relu
    dim3 grid((N_NODES + BM - 1) / BM, 256 / BN);
    gemm_bias_relu<<<grid, 256>>>(agg, W, b, h_out, N_NODES, 256, Fin);
}

extern "C" void kernel_launch(void* const* d_in, const int* in_sizes, int n_in,
                              void* d_out, int out_size)
{
    const float* x  = (const float*)d_in[0];       // [50000,128]
    const void*  ei = d_in[1];                     // [2,800000] int32 OR int64
    const float* W1 = (const float*)d_in[2];       // [128,256]
    const float* b1 = (const float*)d_in[3];
    const float* W2 = (const float*)d_in[4];       // [256,256]
    const float* b2 = (const float*)d_in[5];
    const float* W3 = (const float*)d_in[6];       // [256,256]
    const float* b3 = (const float*)d_in[7];
    float* out = (float*)d_out;                    // [50000,256]

    float* g_h_ptr;
    float* g_agg_ptr;
    cudaGetSymbolAddress((void**)&g_h_ptr, g_h);
    cudaGetSymbolAddress((void**)&g_agg_ptr, g_agg);

    // Determine edge_index dtype on-device (deterministic; cheap).
    detect_idx_dtype<<<1, 32>>>((const long long*)ei);

    // Layer 1: agg(x) [128] -> gemm 128->256 -> g_h
    run_layer(x, 128, ei, W1, b1, g_agg_ptr, g_h_ptr);
    // Layer 2: agg(g_h) [256] -> gemm 256->256 -> g_h
    run_layer(g_h_ptr, 256, ei, W2, b2, g_agg_ptr, g_h_ptr);
    // Layer 3: agg(g_h) [256] -> gemm 256->256 -> out
    run_layer(g_h_ptr, 256, ei, W3, b3, g_agg_ptr, out);
}

// round 3
// speedup vs baseline: 1.3439x; 1.3439x over previous
#include <cuda_runtime.h>
#include <cstdint>

// ---------------------------------------------------------------------------
// GCN: 3 layers of  h = relu(segment_sum_{(s->d)}(h_prev[s]) @ W + b)
// Aggregate-before-transform (segment_sum is linear).
// This round: CSR aggregation (no atomics) + f32x2 packed-FMA GEMM.
// ---------------------------------------------------------------------------

#define N_NODES 50000
#define N_EDGES 800000
#define FMAX    256

// Scratch (static device globals — no runtime allocation).
__device__ float g_h[(size_t)N_NODES * FMAX];    // layer activations
__device__ float g_agg[(size_t)N_NODES * FMAX];  // per-layer aggregation
__device__ int   g_idx_is64;                     // 1 if edge_index is int64
__device__ int   g_counts[N_NODES];              // in-degree histogram
__device__ int   g_offsets[N_NODES + 1];         // CSR row offsets (by dst)
__device__ int   g_cursor[N_NODES];              // fill cursors
__device__ int   g_perm_src[N_EDGES];            // src ids grouped by dst

// ---------------------------------------------------------------------------
// Edge-index dtype probe (JAX may have downcast int64 -> int32).
// ---------------------------------------------------------------------------
__global__ void detect_idx_dtype(const long long* __restrict__ ei64)
{
    if (threadIdx.x == 0 && blockIdx.x == 0) {
        int ok = 1;
        for (int i = 0; i < 256; i++) {
            long long v = ei64[i];
            if (v < 0 || v >= N_NODES) { ok = 0; break; }
        }
        g_idx_is64 = ok;
    }
}

__device__ __forceinline__ int load_idx(const void* ei, long long pos)
{
    long long v;
    if (g_idx_is64) v = ((const long long*)ei)[pos];
    else            v = ((const int*)ei)[pos];
    // degrade to skip instead of crash on bad data
    if ((unsigned long long)v >= N_NODES) return -1;
    return (int)v;
}

// ---------------------------------------------------------------------------
// CSR build: histogram -> single-block scan -> permuted fill.
// ---------------------------------------------------------------------------
__global__ __launch_bounds__(256) void hist_kernel(const void* __restrict__ ei)
{
    int e = blockIdx.x * blockDim.x + threadIdx.x;
    if (e >= N_EDGES) return;
    int d = load_idx(ei, (long long)N_EDGES + e);
    if (d >= 0) atomicAdd(&g_counts[d], 1);
}

__global__ __launch_bounds__(1024) void scan_kernel()
{
    __shared__ int partial[1024];
    int t = threadIdx.x;
    const int CHUNK = (N_NODES + 1023) / 1024;   // 49
    int beg = t * CHUNK;
    int end = beg + CHUNK; if (end > N_NODES) end = N_NODES;
    if (beg > N_NODES) beg = N_NODES;

    int s = 0;
    for (int i = beg; i < end; i++) s += g_counts[i];
    partial[t] = s;
    __syncthreads();
    // Hillis-Steele inclusive scan
    for (int off = 1; off < 1024; off <<= 1) {
        int v = (t >= off) ? partial[t - off] : 0;
        __syncthreads();
        partial[t] += v;
        __syncthreads();
    }
    int prefix = (t == 0) ? 0 : partial[t - 1];
    for (int i = beg; i < end; i++) {
        g_offsets[i] = prefix;
        g_cursor[i]  = prefix;
        prefix += g_counts[i];
    }
    if (t == 1023) g_offsets[N_NODES] = partial[1023];
}

__global__ __launch_bounds__(256) void fill_kernel(const void* __restrict__ ei)
{
    int e = blockIdx.x * blockDim.x + threadIdx.x;
    if (e >= N_EDGES) return;
    int d = load_idx(ei, (long long)N_EDGES + e);
    int s = load_idx(ei, e);
    if (d < 0 || s < 0) return;
    int pos = atomicAdd(&g_cursor[d], 1);
    g_perm_src[pos] = s;
}

// ---------------------------------------------------------------------------
// CSR aggregation: agg[n] = sum_{s in in(n)} h[s].  float4 per thread,
// F/4 threads per node, coalesced row gathers, one streaming write, no atomics.
// ---------------------------------------------------------------------------
template <int F>
__global__ __launch_bounds__(256) void aggregate_csr(
    const float* __restrict__ h,
    float* __restrict__ agg)
{
    constexpr int CH  = F / 4;        // threads per node
    constexpr int NPB = 256 / CH;     // nodes per block
    int node = blockIdx.x * NPB + threadIdx.x / CH;
    int c    = threadIdx.x % CH;
    if (node >= N_NODES) return;

    int beg = g_offsets[node];
    int end = g_offsets[node + 1];

    float4 acc = make_float4(0.f, 0.f, 0.f, 0.f);
    int i = beg;
    for (; i + 4 <= end; i += 4) {
        int s0 = g_perm_src[i + 0];
        int s1 = g_perm_src[i + 1];
        int s2 = g_perm_src[i + 2];
        int s3 = g_perm_src[i + 3];
        float4 v0 = *reinterpret_cast<const float4*>(h + (size_t)s0 * F + c * 4);
        float4 v1 = *reinterpret_cast<const float4*>(h + (size_t)s1 * F + c * 4);
        float4 v2 = *reinterpret_cast<const float4*>(h + (size_t)s2 * F + c * 4);
        float4 v3 = *reinterpret_cast<const float4*>(h + (size_t)s3 * F + c * 4);
        acc.x += v0.x + v1.x + v2.x + v3.x;
        acc.y += v0.y + v1.y + v2.y + v3.y;
        acc.z += v0.z + v1.z + v2.z + v3.z;
        acc.w += v0.w + v1.w + v2.w + v3.w;
    }
    for (; i < end; i++) {
        int s = g_perm_src[i];
        float4 v = *reinterpret_cast<const float4*>(h + (size_t)s * F + c * 4);
        acc.x += v.x; acc.y += v.y; acc.z += v.z; acc.w += v.w;
    }
    *reinterpret_cast<float4*>(agg + (size_t)node * F + c * 4) = acc;
}

// ---------------------------------------------------------------------------
// f32x2 packed-FMA GEMM + bias + ReLU:  C = relu(A[M,K] @ W[K,N] + b)
// BM=BN=128, BK=16, 256 threads, 8x8 microtile, FFMA2 inner loop.
// A stored pre-duplicated in SMEM so the inner loop has zero packing movs.
// ---------------------------------------------------------------------------
#define GBM 128
#define GBN 128
#define GBK 16

__device__ __forceinline__ void fma2(unsigned long long& acc,
                                     unsigned long long a,
                                     unsigned long long w)
{
    asm("fma.rn.f32x2 %0, %1, %2, %0;" : "+l"(acc) : "l"(a), "l"(w));
}

__device__ __forceinline__ unsigned long long dup2(float v)
{
    unsigned long long r;
    asm("mov.b64 %0, {%1, %1};" : "=l"(r) : "f"(v));
    return r;
}

__device__ __forceinline__ float2 unpack2(unsigned long long p)
{
    float2 f;
    asm("mov.b64 {%0, %1}, %2;" : "=f"(f.x), "=f"(f.y) : "l"(p));
    return f;
}

__global__ __launch_bounds__(256) void gemm_bias_relu_f32x2(
    const float* __restrict__ A,
    const float* __restrict__ W,
    const float* __restrict__ bias,
    float* __restrict__ C,
    int M, int N, int K)
{
    __shared__ unsigned long long As2[GBK][GBM]; // duplicated (v,v) pairs, 16KB
    __shared__ float Ws[GBK][GBN];               // 8KB

    int tid  = threadIdx.x;
    int brow = blockIdx.x * GBM;
    int bcol = blockIdx.y * GBN;

    int ty = tid >> 4;          // 0..15 (row group)
    int tx = tid & 15;          // 0..15 (col group)

    unsigned long long acc2[8][4];
    #pragma unroll
    for (int r = 0; r < 8; r++)
        #pragma unroll
        for (int j = 0; j < 4; j++)
            acc2[r][j] = 0ull;

    // ---- global load mappings ----
    // A tile: 128 rows x 16 k = 512 float4; thread loads q=tid and q=tid+256.
    //   q -> row = q>>2 (0..127), kg = q&3, k = kg*4
    int a_r0 = tid >> 2;               // 0..63
    int a_kg = (tid & 3) * 4;          // 0,4,8,12
    // W tile: 16 k x 128 n = 512 float4; q -> krow = q>>5, n = (q&31)*4
    int w_k0 = tid >> 5;               // 0..7
    int w_n  = (tid & 31) * 4;

    for (int k0 = 0; k0 < K; k0 += GBK) {
        // load A (rows clamped; tail stores are guarded in epilogue)
        #pragma unroll
        for (int half = 0; half < 2; half++) {
            int r = a_r0 + half * 64;
            int grow = brow + r; if (grow >= M) grow = M - 1;
            float4 av = *reinterpret_cast<const float4*>(
                A + (size_t)grow * K + k0 + a_kg);
            As2[a_kg + 0][r] = dup2(av.x);
            As2[a_kg + 1][r] = dup2(av.y);
            As2[a_kg + 2][r] = dup2(av.z);
            As2[a_kg + 3][r] = dup2(av.w);
        }
        // load W
        #pragma unroll
        for (int half = 0; half < 2; half++) {
            int kr = w_k0 + half * 8;
            float4 wv = *reinterpret_cast<const float4*>(
                W + (size_t)(k0 + kr) * N + bcol + w_n);
            *reinterpret_cast<float4*>(&Ws[kr][w_n]) = wv;
        }
        __syncthreads();

        #pragma unroll
        for (int kk = 0; kk < GBK; kk++) {
            // a dups: 8 consecutive pairs = 4x LDS.128
            ulonglong2 a01 = *reinterpret_cast<const ulonglong2*>(&As2[kk][ty * 8 + 0]);
            ulonglong2 a23 = *reinterpret_cast<const ulonglong2*>(&As2[kk][ty * 8 + 2]);
            ulonglong2 a45 = *reinterpret_cast<const ulonglong2*>(&As2[kk][ty * 8 + 4]);
            ulonglong2 a67 = *reinterpret_cast<const ulonglong2*>(&As2[kk][ty * 8 + 6]);
            // w pairs: 8 floats = 4 packed pairs = 2x LDS.128
            ulonglong2 w03 = *reinterpret_cast<const ulonglong2*>(&Ws[kk][tx * 8 + 0]);
            ulonglong2 w47 = *reinterpret_cast<const ulonglong2*>(&Ws[kk][tx * 8 + 4]);

            unsigned long long a[8] = { a01.x, a01.y, a23.x, a23.y,
                                        a45.x, a45.y, a67.x, a67.y };
            unsigned long long w[4] = { w03.x, w03.y, w47.x, w47.y };

            #pragma unroll
            for (int r = 0; r < 8; r++) {
                fma2(acc2[r][0], a[r], w[0]);
                fma2(acc2[r][1], a[r], w[1]);
                fma2(acc2[r][2], a[r], w[2]);
                fma2(acc2[r][3], a[r], w[3]);
            }
        }
        __syncthreads();
    }

    // epilogue: bias + relu + store
    float bvals[8];
    #pragma unroll
    for (int j = 0; j < 8; j += 4) {
        float4 b4 = *reinterpret_cast<const float4*>(bias + bcol + tx * 8 + j);
        bvals[j + 0] = b4.x; bvals[j + 1] = b4.y;
        bvals[j + 2] = b4.z; bvals[j + 3] = b4.w;
    }

    #pragma unroll
    for (int r = 0; r < 8; r++) {
        int row = brow + ty * 8 + r;
        if (row >= M) continue;
        float out[8];
        #pragma unroll
        for (int j = 0; j < 4; j++) {
            float2 f = unpack2(acc2[r][j]);
            out[2 * j + 0] = fmaxf(f.x + bvals[2 * j + 0], 0.f);
            out[2 * j + 1] = fmaxf(f.y + bvals[2 * j + 1], 0.f);
        }
        float* crow = C + (size_t)row * N + bcol + tx * 8;
        *reinterpret_cast<float4*>(crow + 0) = make_float4(out[0], out[1], out[2], out[3]);
        *reinterpret_cast<float4*>(crow + 4) = make_float4(out[4], out[5], out[6], out[7]);
    }
}

// ---------------------------------------------------------------------------
// Launch orchestration
// ---------------------------------------------------------------------------
static inline void run_layer(const float* h_in, int Fin,
                             const float* W, const float* b,
                             float* agg, float* h_out)
{
    if (Fin == 128) {
        aggregate_csr<128><<<(N_NODES + 7) / 8, 256>>>(h_in, agg);
    } else {
        aggregate_csr<256><<<(N_NODES + 3) / 4, 256>>>(h_in, agg);
    }
    dim3 grid((N_NODES + GBM - 1) / GBM, 256 / GBN);
    gemm_bias_relu_f32x2<<<grid, 256>>>(agg, W, b, h_out, N_NODES, 256, Fin);
}

extern "C" void kernel_launch(void* const* d_in, const int* in_sizes, int n_in,
                              void* d_out, int out_size)
{
    const float* x  = (const float*)d_in[0];       // [50000,128]
    const void*  ei = d_in[1];                     // [2,800000] int32 OR int64
    const float* W1 = (const float*)d_in[2];       // [128,256]
    const float* b1 = (const float*)d_in[3];
    const float* W2 = (const float*)d_in[4];       // [256,256]
    const float* b2 = (const float*)d_in[5];
    const float* W3 = (const float*)d_in[6];       // [256,256]
    const float* b3 = (const float*)d_in[7];
    float* out = (float*)d_out;                    // [50000,256]

    float* g_h_ptr;   cudaGetSymbolAddress((void**)&g_h_ptr, g_h);
    float* g_agg_ptr; cudaGetSymbolAddress((void**)&g_agg_ptr, g_agg);
    int*   g_counts_ptr; cudaGetSymbolAddress((void**)&g_counts_ptr, g_counts);

    // dtype probe + CSR build (once per launch, reused by all 3 layers)
    detect_idx_dtype<<<1, 32>>>((const long long*)ei);
    cudaMemsetAsync(g_counts_ptr, 0, N_NODES * sizeof(int), 0);
    hist_kernel<<<(N_EDGES + 255) / 256, 256>>>(ei);
    scan_kernel<<<1, 1024>>>();
    fill_kernel<<<(N_EDGES + 255) / 256, 256>>>(ei);

    // Layer 1: agg(x)[128] -> gemm 128->256 -> g_h
    run_layer(x, 128, W1, b1, g_agg_ptr, g_h_ptr);
    // Layer 2
    run_layer(g_h_ptr, 256, W2, b2, g_agg_ptr, g_h_ptr);
    // Layer 3 -> out
    run_layer(g_h_ptr, 256, W3, b3, g_agg_ptr, out);
}

// round 4
// speedup vs baseline: 1.4150x; 1.0529x over previous
#include <cuda_runtime.h>
#include <cstdint>

// ---------------------------------------------------------------------------
// GCN: 3 layers of  h = relu(segment_sum_{(s->d)}(h_prev[s]) @ W + b)
// Aggregate-before-transform (segment_sum is linear).
// Round 3: tensor-core GEMM via 3xTF32 mma.sync (fp32-accurate).
// ---------------------------------------------------------------------------

#define N_NODES 50000
#define N_EDGES 800000
#define FMAX    256

// Scratch (static device globals — no runtime allocation).
__device__ float g_h[(size_t)N_NODES * FMAX];    // layer activations
__device__ float g_agg[(size_t)N_NODES * FMAX];  // per-layer aggregation
__device__ int   g_idx_is64;                     // 1 if edge_index is int64
__device__ int   g_counts[N_NODES];              // in-degree histogram
__device__ int   g_offsets[N_NODES + 1];         // CSR row offsets (by dst)
__device__ int   g_cursor[N_NODES];              // fill cursors
__device__ int   g_perm_src[N_EDGES];            // src ids grouped by dst

// ---------------------------------------------------------------------------
// Edge-index dtype probe (JAX may have downcast int64 -> int32).
// ---------------------------------------------------------------------------
__global__ void detect_idx_dtype(const long long* __restrict__ ei64)
{
    if (threadIdx.x == 0 && blockIdx.x == 0) {
        int ok = 1;
        for (int i = 0; i < 256; i++) {
            long long v = ei64[i];
            if (v < 0 || v >= N_NODES) { ok = 0; break; }
        }
        g_idx_is64 = ok;
    }
}

__device__ __forceinline__ int load_idx(const void* ei, long long pos)
{
    long long v;
    if (g_idx_is64) v = ((const long long*)ei)[pos];
    else            v = ((const int*)ei)[pos];
    if ((unsigned long long)v >= N_NODES) return -1;   // degrade, don't crash
    return (int)v;
}

// ---------------------------------------------------------------------------
// CSR build: histogram -> single-block scan -> permuted fill.
// ---------------------------------------------------------------------------
__global__ __launch_bounds__(256) void hist_kernel(const void* __restrict__ ei)
{
    int e = blockIdx.x * blockDim.x + threadIdx.x;
    if (e >= N_EDGES) return;
    int d = load_idx(ei, (long long)N_EDGES + e);
    if (d >= 0) atomicAdd(&g_counts[d], 1);
}

__global__ __launch_bounds__(1024) void scan_kernel()
{
    __shared__ int partial[1024];
    int t = threadIdx.x;
    const int CHUNK = (N_NODES + 1023) / 1024;   // 49
    int beg = t * CHUNK;
    int end = beg + CHUNK; if (end > N_NODES) end = N_NODES;
    if (beg > N_NODES) beg = N_NODES;

    int s = 0;
    for (int i = beg; i < end; i++) s += g_counts[i];
    partial[t] = s;
    __syncthreads();
    for (int off = 1; off < 1024; off <<= 1) {
        int v = (t >= off) ? partial[t - off] : 0;
        __syncthreads();
        partial[t] += v;
        __syncthreads();
    }
    int prefix = (t == 0) ? 0 : partial[t - 1];
    for (int i = beg; i < end; i++) {
        g_offsets[i] = prefix;
        g_cursor[i]  = prefix;
        prefix += g_counts[i];
    }
    if (t == 1023) g_offsets[N_NODES] = partial[1023];
}

__global__ __launch_bounds__(256) void fill_kernel(const void* __restrict__ ei)
{
    int e = blockIdx.x * blockDim.x + threadIdx.x;
    if (e >= N_EDGES) return;
    int d = load_idx(ei, (long long)N_EDGES + e);
    int s = load_idx(ei, e);
    if (d < 0 || s < 0) return;
    int pos = atomicAdd(&g_cursor[d], 1);
    g_perm_src[pos] = s;
}

// ---------------------------------------------------------------------------
// CSR aggregation: agg[n] = sum_{s in in(n)} h[s].  float4 per thread,
// F/4 threads per node, coalesced row gathers, one streaming write, no atomics.
// ---------------------------------------------------------------------------
template <int F>
__global__ __launch_bounds__(256) void aggregate_csr(
    const float* __restrict__ h,
    float* __restrict__ agg)
{
    constexpr int CH  = F / 4;
    constexpr int NPB = 256 / CH;
    int node = blockIdx.x * NPB + threadIdx.x / CH;
    int c    = threadIdx.x % CH;
    if (node >= N_NODES) return;

    int beg = g_offsets[node];
    int end = g_offsets[node + 1];

    float4 acc = make_float4(0.f, 0.f, 0.f, 0.f);
    int i = beg;
    for (; i + 4 <= end; i += 4) {
        int s0 = g_perm_src[i + 0];
        int s1 = g_perm_src[i + 1];
        int s2 = g_perm_src[i + 2];
        int s3 = g_perm_src[i + 3];
        float4 v0 = *reinterpret_cast<const float4*>(h + (size_t)s0 * F + c * 4);
        float4 v1 = *reinterpret_cast<const float4*>(h + (size_t)s1 * F + c * 4);
        float4 v2 = *reinterpret_cast<const float4*>(h + (size_t)s2 * F + c * 4);
        float4 v3 = *reinterpret_cast<const float4*>(h + (size_t)s3 * F + c * 4);
        acc.x += v0.x + v1.x + v2.x + v3.x;
        acc.y += v0.y + v1.y + v2.y + v3.y;
        acc.z += v0.z + v1.z + v2.z + v3.z;
        acc.w += v0.w + v1.w + v2.w + v3.w;
    }
    for (; i < end; i++) {
        int s = g_perm_src[i];
        float4 v = *reinterpret_cast<const float4*>(h + (size_t)s * F + c * 4);
        acc.x += v.x; acc.y += v.y; acc.z += v.z; acc.w += v.w;
    }
    *reinterpret_cast<float4*>(agg + (size_t)node * F + c * 4) = acc;
}

// ---------------------------------------------------------------------------
// 3xTF32 tensor-core GEMM + bias + ReLU:  C = relu(A[M,K] @ W[K,N] + b)
// BM=BN=128, BK=16, 256 threads (8 warps, 4x2 grid), m16n8k8 atoms.
// Each operand split v = hi + lo (tf32 + residual); 3 MMAs per atom recover
// fp32 precision (missing lo*lo term ~2^-22 relative).
// ---------------------------------------------------------------------------
#define GBM 128
#define GBN 128
#define GBK 16
#define SSTR 136   // SMEM row stride (floats): 128 + 8 pad -> conflict-free frags

__device__ __forceinline__ unsigned f2tf32(float v)
{
    unsigned r;
    asm("cvt.rna.tf32.f32 %0, %1;" : "=r"(r) : "f"(v));
    return r;
}

__device__ __forceinline__ void mma_tf32(float* c, const unsigned* a, const unsigned* b)
{
    asm volatile(
        "mma.sync.aligned.m16n8k8.row.col.f32.tf32.tf32.f32 "
        "{%0,%1,%2,%3}, {%4,%5,%6,%7}, {%8,%9}, {%0,%1,%2,%3};"
        : "+f"(c[0]), "+f"(c[1]), "+f"(c[2]), "+f"(c[3])
        : "r"(a[0]), "r"(a[1]), "r"(a[2]), "r"(a[3]),
          "r"(b[0]), "r"(b[1]));
}

__global__ __launch_bounds__(256) void gemm_bias_relu_tf32(
    const float* __restrict__ A,
    const float* __restrict__ W,
    const float* __restrict__ bias,
    float* __restrict__ C,
    int M, int N, int K)
{
    // SMEM tiles, k-major, stride-padded. ~34.8 KB total.
    __shared__ unsigned As_hi[GBK][SSTR];
    __shared__ unsigned As_lo[GBK][SSTR];
    __shared__ unsigned Ws_hi[GBK][SSTR];
    __shared__ unsigned Ws_lo[GBK][SSTR];

    int tid  = threadIdx.x;
    int lane = tid & 31;
    int wid  = tid >> 5;              // 0..7
    int warp_m = wid & 3;             // 4 warps along M (32 rows each)
    int warp_n = wid >> 2;            // 2 warps along N (64 cols each)
    int g = lane >> 2;                // 0..7
    int c = lane & 3;                 // 0..3

    int brow = blockIdx.x * GBM;
    int bcol = blockIdx.y * GBN;

    // acc[m_atom(2)][n_atom(8)][4]
    float acc[2][8][4];
    #pragma unroll
    for (int ma = 0; ma < 2; ma++)
        #pragma unroll
        for (int na = 0; na < 8; na++)
            #pragma unroll
            for (int j = 0; j < 4; j++) acc[ma][na][j] = 0.f;

    // Global load mappings.
    int a_r0 = tid >> 2;              // 0..63 (+64 second half)
    int a_kg = (tid & 3) * 4;         // 0,4,8,12
    int w_k0 = tid >> 5;              // 0..7 (+8 second half)
    int w_n  = (tid & 31) * 4;

    for (int k0 = 0; k0 < K; k0 += GBK) {
        // A tile -> transposed (k-major), hi/lo split, scalar stores.
        #pragma unroll
        for (int half = 0; half < 2; half++) {
            int r = a_r0 + half * 64;
            int grow = brow + r; if (grow >= M) grow = M - 1;
            float4 av = *reinterpret_cast<const float4*>(
                A + (size_t)grow * K + k0 + a_kg);
            float vv[4] = { av.x, av.y, av.z, av.w };
            #pragma unroll
            for (int j = 0; j < 4; j++) {
                unsigned hi = f2tf32(vv[j]);
                float lo = vv[j] - __uint_as_float(hi);
                As_hi[a_kg + j][r] = hi;
                As_lo[a_kg + j][r] = f2tf32(lo);
            }
        }
        // W tile (row-major k x n), hi/lo split.
        #pragma unroll
        for (int half = 0; half < 2; half++) {
            int kr = w_k0 + half * 8;
            float4 wv = *reinterpret_cast<const float4*>(
                W + (size_t)(k0 + kr) * N + bcol + w_n);
            float vv[4] = { wv.x, wv.y, wv.z, wv.w };
            #pragma unroll
            for (int j = 0; j < 4; j++) {
                unsigned hi = f2tf32(vv[j]);
                float lo = vv[j] - __uint_as_float(hi);
                Ws_hi[kr][w_n + j] = hi;
                Ws_lo[kr][w_n + j] = f2tf32(lo);
            }
        }
        __syncthreads();

        #pragma unroll
        for (int kq = 0; kq < 2; kq++) {
            int kk = kq * 8 + c;

            // A fragments: 2 m-atoms x 4 regs, hi+lo.
            unsigned a_hi[2][4], a_lo[2][4];
            #pragma unroll
            for (int ma = 0; ma < 2; ma++) {
                int r0 = warp_m * 32 + ma * 16 + g;
                a_hi[ma][0] = As_hi[kk    ][r0];
                a_hi[ma][1] = As_hi[kk    ][r0 + 8];
                a_hi[ma][2] = As_hi[kk + 4][r0];
                a_hi[ma][3] = As_hi[kk + 4][r0 + 8];
                a_lo[ma][0] = As_lo[kk    ][r0];
                a_lo[ma][1] = As_lo[kk    ][r0 + 8];
                a_lo[ma][2] = As_lo[kk + 4][r0];
                a_lo[ma][3] = As_lo[kk + 4][r0 + 8];
            }
            // B fragments: 8 n-atoms x 2 regs, hi+lo.
            unsigned b_hi[8][2], b_lo[8][2];
            #pragma unroll
            for (int na = 0; na < 8; na++) {
                int col = warp_n * 64 + na * 8 + g;
                b_hi[na][0] = Ws_hi[kk    ][col];
                b_hi[na][1] = Ws_hi[kk + 4][col];
                b_lo[na][0] = Ws_lo[kk    ][col];
                b_lo[na][1] = Ws_lo[kk + 4][col];
            }

            #pragma unroll
            for (int ma = 0; ma < 2; ma++)
                #pragma unroll
                for (int na = 0; na < 8; na++) {
                    mma_tf32(acc[ma][na], a_hi[ma], b_hi[na]);
                    mma_tf32(acc[ma][na], a_hi[ma], b_lo[na]);
                    mma_tf32(acc[ma][na], a_lo[ma], b_hi[na]);
                }
        }
        __syncthreads();
    }

    // Epilogue: bias + relu + float2 stores.
    #pragma unroll
    for (int na = 0; na < 8; na++) {
        int col = bcol + warp_n * 64 + na * 8 + c * 2;
        float b0 = bias[col];
        float b1 = bias[col + 1];
        #pragma unroll
        for (int ma = 0; ma < 2; ma++) {
            int row0 = brow + warp_m * 32 + ma * 16 + g;
            if (row0 < M) {
                float2 o;
                o.x = fmaxf(acc[ma][na][0] + b0, 0.f);
                o.y = fmaxf(acc[ma][na][1] + b1, 0.f);
                *reinterpret_cast<float2*>(C + (size_t)row0 * N + col) = o;
            }
            int row1 = row0 + 8;
            if (row1 < M) {
                float2 o;
                o.x = fmaxf(acc[ma][na][2] + b0, 0.f);
                o.y = fmaxf(acc[ma][na][3] + b1, 0.f);
                *reinterpret_cast<float2*>(C + (size_t)row1 * N + col) = o;
            }
        }
    }
}

// ---------------------------------------------------------------------------
// Launch orchestration
// ---------------------------------------------------------------------------
static inline void run_layer(const float* h_in, int Fin,
                             const float* W, const float* b,
                             float* agg, float* h_out)
{
    if (Fin == 128) {
        aggregate_csr<128><<<(N_NODES + 7) / 8, 256>>>(h_in, agg);
    } else {
        aggregate_csr<256><<<(N_NODES + 3) / 4, 256>>>(h_in, agg);
    }
    dim3 grid((N_NODES + GBM - 1) / GBM, 256 / GBN);
    gemm_bias_relu_tf32<<<grid, 256>>>(agg, W, b, h_out, N_NODES, 256, Fin);
}

extern "C" void kernel_launch(void* const* d_in, const int* in_sizes, int n_in,
                              void* d_out, int out_size)
{
    const float* x  = (const float*)d_in[0];       // [50000,128]
    const void*  ei = d_in[1];                     // [2,800000] int32 OR int64
    const float* W1 = (const float*)d_in[2];       // [128,256]
    const float* b1 = (const float*)d_in[3];
    const float* W2 = (const float*)d_in[4];       // [256,256]
    const float* b2 = (const float*)d_in[5];
    const float* W3 = (const float*)d_in[6];       // [256,256]
    const float* b3 = (const float*)d_in[7];
    float* out = (float*)d_out;                    // [50000,256]

    float* g_h_ptr;   cudaGetSymbolAddress((void**)&g_h_ptr, g_h);
    float* g_agg_ptr; cudaGetSymbolAddress((void**)&g_agg_ptr, g_agg);
    int*   g_counts_ptr; cudaGetSymbolAddress((void**)&g_counts_ptr, g_counts);

    // dtype probe + CSR build (once per launch, reused by all 3 layers)
    detect_idx_dtype<<<1, 32>>>((const long long*)ei);
    cudaMemsetAsync(g_counts_ptr, 0, N_NODES * sizeof(int), 0);
    hist_kernel<<<(N_EDGES + 255) / 256, 256>>>(ei);
    scan_kernel<<<1, 1024>>>();
    fill_kernel<<<(N_EDGES + 255) / 256, 256>>>(ei);

    // Layer 1: agg(x)[128] -> gemm 128->256 -> g_h
    run_layer(x, 128, W1, b1, g_agg_ptr, g_h_ptr);
    // Layer 2
    run_layer(g_h_ptr, 256, W2, b2, g_agg_ptr, g_h_ptr);
    // Layer 3 -> out
    run_layer(g_h_ptr, 256, W3, b3, g_agg_ptr, out);
}